// round 8
// baseline (speedup 1.0000x reference)
#include <cuda_runtime.h>
#include <cuda_bf16.h>
#include <cstddef>

#define N_NODES   50000
#define N_GRAPHS  128
#define IN_C      128
#define HID_C     128
#define OUT_C     64
#define E_MAX     700000

// ---------------- device scratch (no allocations allowed) ----------------
__device__ int   g_degi[N_NODES];        // in-degree (by dst)
__device__ int   g_off [N_NODES + 1];    // CSR row offsets (by dst)
__device__ int   g_cur [N_NODES];        // fill cursors
__device__ int   g_csr [E_MAX];          // src ids grouped by dst
__device__ float g_dinv[N_NODES];
__device__ float g_g1  [(size_t)N_NODES * HID_C];   // dinv * (x @ W1)
__device__ float g_t   [(size_t)N_NODES * HID_C];   // relu(layer-1 out)
__device__ float g_g2  [(size_t)N_NODES * OUT_C];   // dinv * (t @ W2)
__device__ float g_gsum[N_GRAPHS * OUT_C];
__device__ float g_gcnt[N_GRAPHS];

__device__ __forceinline__ float4 f4add(float4 a, float4 b) {
    return make_float4(a.x + b.x, a.y + b.y, a.z + b.z, a.w + b.w);
}
__device__ __forceinline__ void red_add_v2(float* p, float2 v) {
    asm volatile("red.global.add.v2.f32 [%0], {%1, %2};"
                 :: "l"(p), "f"(v.x), "f"(v.y) : "memory");
}

// ---------------- degree (by dst) ----------------
__global__ void deg_kernel(const int* __restrict__ dst, int E) {
    int e = blockIdx.x * blockDim.x + threadIdx.x;
    if (e < E) atomicAdd(&g_degi[dst[e]], 1);
}

// ---------------- exclusive scan of degrees + cursors + dinv (1 block) ----------------
__global__ void scan_kernel(int N) {
    __shared__ int ssum[1024];
    const int tid = threadIdx.x;
    const int C   = (N + 1023) / 1024;
    const int lo  = tid * C;
    const int hi  = min(lo + C, N);

    int s = 0;
    for (int i = lo; i < hi; i++) s += g_degi[i];
    ssum[tid] = s;
    __syncthreads();
    for (int off = 1; off < 1024; off <<= 1) {
        int v = (tid >= off) ? ssum[tid - off] : 0;
        __syncthreads();
        ssum[tid] += v;
        __syncthreads();
    }
    int running = ssum[tid] - s;
    for (int i = lo; i < hi; i++) {
        g_off[i] = running;
        g_cur[i] = running;
        int d = g_degi[i];
        g_dinv[i] = rsqrtf((float)(1 + d));   // +1 self-loop
        running += d;
    }
    if (tid == 1023) g_off[N] = ssum[1023];
}

// ---------------- CSR fill: bucket srcs by dst ----------------
__global__ void fill_kernel(const int* __restrict__ src,
                            const int* __restrict__ dst,
                            int E) {
    int e = blockIdx.x * blockDim.x + threadIdx.x;
    if (e < E) {
        int pos = atomicAdd(&g_cur[dst[e]], 1);
        g_csr[pos] = src[e];
    }
}

// ---------------- classic double-buffered SGEMM ----------------
// C[M,BN] = dinv ⊙ (A[M,128] @ B[128,BN]).  BM=128, BK=8, 256 threads.
template<int BN, int TN>
__global__ void __launch_bounds__(256, 2)
sgemm_kernel(const float* __restrict__ A,
             const float* __restrict__ B,
             float* __restrict__ C, int M) {
    __shared__ __align__(16) float As[2][8][128];
    __shared__ __align__(16) float Bs[2][8][BN];

    const int tid  = threadIdx.x;
    const int tx   = tid & 15;
    const int ty   = tid >> 4;
    const int row0 = blockIdx.x * 128;

    const int am = tid >> 1;
    const int ak = (tid & 1) * 4;
    const int bk  = (BN == 128) ? (tid >> 5) : (tid >> 4);
    const int bc4 = (BN == 128) ? (tid & 31) : (tid & 15);
    const bool bAct = (BN == 128) ? true : (tid < 128);

    float acc[8][TN];
#pragma unroll
    for (int i = 0; i < 8; i++)
#pragma unroll
        for (int j = 0; j < TN; j++) acc[i][j] = 0.f;

    auto gloadA = [&](int k0) -> float4 {
        int grow = row0 + am;
        float4 v = make_float4(0.f, 0.f, 0.f, 0.f);
        if (grow < M)
            v = *(const float4*)(A + (size_t)grow * 128 + k0 + ak);
        return v;
    };
    auto gloadB = [&](int k0) -> float4 {
        if (!bAct) return make_float4(0.f, 0.f, 0.f, 0.f);
        return *(const float4*)(B + (size_t)(k0 + bk) * BN + bc4 * 4);
    };
    auto storeA = [&](int buf, float4 v) {
        As[buf][ak + 0][am] = v.x;
        As[buf][ak + 1][am] = v.y;
        As[buf][ak + 2][am] = v.z;
        As[buf][ak + 3][am] = v.w;
    };
    auto storeB = [&](int buf, float4 v) {
        if (bAct) *(float4*)(&Bs[buf][bk][bc4 * 4]) = v;
    };

    storeA(0, gloadA(0));
    storeB(0, gloadB(0));
    __syncthreads();

#pragma unroll 1
    for (int t = 0; t < 16; t++) {
        const int cur = t & 1;
        float4 pa, pb;
        if (t < 15) {
            pa = gloadA((t + 1) * 8);
            pb = gloadB((t + 1) * 8);
        }
#pragma unroll
        for (int k = 0; k < 8; k++) {
            float a[8];
            float4 a0 = *(const float4*)(&As[cur][k][ty * 8]);
            float4 a1 = *(const float4*)(&As[cur][k][ty * 8 + 4]);
            a[0] = a0.x; a[1] = a0.y; a[2] = a0.z; a[3] = a0.w;
            a[4] = a1.x; a[5] = a1.y; a[6] = a1.z; a[7] = a1.w;
            float b[TN];
            if (TN == 8) {
                float4 b0 = *(const float4*)(&Bs[cur][k][tx * 8]);
                float4 b1 = *(const float4*)(&Bs[cur][k][tx * 8 + 4]);
                b[0] = b0.x; b[1] = b0.y; b[2] = b0.z; b[3] = b0.w;
                b[4] = b1.x; b[5] = b1.y; b[6] = b1.z; b[7] = b1.w;
            } else {
                float4 b0 = *(const float4*)(&Bs[cur][k][tx * TN]);
                b[0] = b0.x; b[1] = b0.y; b[2] = b0.z; b[3] = b0.w;
            }
#pragma unroll
            for (int i = 0; i < 8; i++)
#pragma unroll
                for (int j = 0; j < TN; j++) acc[i][j] += a[i] * b[j];
        }
        if (t < 15) {
            storeA(cur ^ 1, pa);
            storeB(cur ^ 1, pb);
        }
        __syncthreads();
    }

#pragma unroll
    for (int i = 0; i < 8; i++) {
        int grow = row0 + ty * 8 + i;
        if (grow >= M) break;
        float d = g_dinv[grow];
        float* out = C + (size_t)grow * BN + tx * TN;
#pragma unroll
        for (int j4 = 0; j4 < TN / 4; j4++) {
            float4 v;
            v.x = d * acc[i][j4 * 4 + 0];
            v.y = d * acc[i][j4 * 4 + 1];
            v.z = d * acc[i][j4 * 4 + 2];
            v.w = d * acc[i][j4 * 4 + 3];
            *(float4*)(out + j4 * 4) = v;
        }
    }
}

// ---------------- gather layer 1 (pull, MLP-8): t = relu(dinv*(Σ g1[s] + g1[d]) + b1) ----------------
// one warp per dst node; lane holds float4 (128 floats/row); 8-deep batched loads.
__global__ void __launch_bounds__(256)
gather1_kernel(const float* __restrict__ b1, int N) {
    const int wid  = threadIdx.x >> 5;
    const int lane = threadIdx.x & 31;
    const int node = blockIdx.x * 8 + wid;
    if (node >= N) return;

    const float4* base = (const float4*)g_g1;   // row stride = 32 float4
    int e  = g_off[node];
    const int e1 = g_off[node + 1];

    float4 s0 = base[(size_t)node * 32 + lane];  // self-loop
    float4 s1 = make_float4(0.f, 0.f, 0.f, 0.f);
    float4 s2 = make_float4(0.f, 0.f, 0.f, 0.f);
    float4 s3 = make_float4(0.f, 0.f, 0.f, 0.f);

    for (; e < e1; e += 8) {
        int myidx = -1;
        if (lane < 8 && e + lane < e1) myidx = g_csr[e + lane];
        // broadcast 8 indices, issue 8 independent row loads
        float4 v[8];
        int idx[8];
#pragma unroll
        for (int j = 0; j < 8; j++) idx[j] = __shfl_sync(0xffffffffu, myidx, j);
#pragma unroll
        for (int j = 0; j < 8; j++)
            v[j] = (idx[j] >= 0) ? base[(size_t)idx[j] * 32 + lane]
                                 : make_float4(0.f, 0.f, 0.f, 0.f);
        s0 = f4add(s0, v[0]); s1 = f4add(s1, v[1]);
        s2 = f4add(s2, v[2]); s3 = f4add(s3, v[3]);
        s0 = f4add(s0, v[4]); s1 = f4add(s1, v[5]);
        s2 = f4add(s2, v[6]); s3 = f4add(s3, v[7]);
    }
    float4 v = f4add(f4add(s0, s1), f4add(s2, s3));

    float dv = g_dinv[node];
    float4 bb = ((const float4*)b1)[lane];
    float4 r;
    r.x = fmaxf(dv * v.x + bb.x, 0.f);
    r.y = fmaxf(dv * v.y + bb.y, 0.f);
    r.z = fmaxf(dv * v.z + bb.z, 0.f);
    r.w = fmaxf(dv * v.w + bb.w, 0.f);
    ((float4*)g_t)[(size_t)node * 32 + lane] = r;
}

// ---------------- gather layer 2 (pull, MLP-8) + fused bias + pool RED ----------------
// one warp per dst node; lane holds float2 (64 floats/row).
__global__ void __launch_bounds__(256)
gather2_kernel(const int* __restrict__ batch,
               const float* __restrict__ b2, int N) {
    const int wid  = threadIdx.x >> 5;
    const int lane = threadIdx.x & 31;
    const int node = blockIdx.x * 8 + wid;
    if (node >= N) return;

    const float2* base = (const float2*)g_g2;   // row stride = 32 float2
    int e  = g_off[node];
    const int e1 = g_off[node + 1];

    float2 s0 = base[(size_t)node * 32 + lane];  // self-loop
    float2 s1 = make_float2(0.f, 0.f);
    float2 s2 = make_float2(0.f, 0.f);
    float2 s3 = make_float2(0.f, 0.f);

    for (; e < e1; e += 8) {
        int myidx = -1;
        if (lane < 8 && e + lane < e1) myidx = g_csr[e + lane];
        float2 v[8];
        int idx[8];
#pragma unroll
        for (int j = 0; j < 8; j++) idx[j] = __shfl_sync(0xffffffffu, myidx, j);
#pragma unroll
        for (int j = 0; j < 8; j++)
            v[j] = (idx[j] >= 0) ? base[(size_t)idx[j] * 32 + lane]
                                 : make_float2(0.f, 0.f);
        s0.x += v[0].x; s0.y += v[0].y;  s1.x += v[1].x; s1.y += v[1].y;
        s2.x += v[2].x; s2.y += v[2].y;  s3.x += v[3].x; s3.y += v[3].y;
        s0.x += v[4].x; s0.y += v[4].y;  s1.x += v[5].x; s1.y += v[5].y;
        s2.x += v[6].x; s2.y += v[6].y;  s3.x += v[7].x; s3.y += v[7].y;
    }
    float2 v;
    v.x = (s0.x + s1.x) + (s2.x + s3.x);
    v.y = (s0.y + s1.y) + (s2.y + s3.y);

    float dv = g_dinv[node];
    float2 bb = ((const float2*)b2)[lane];
    float2 r;
    r.x = dv * v.x + bb.x;
    r.y = dv * v.y + bb.y;

    int b = batch[node];
    red_add_v2(g_gsum + b * OUT_C + lane * 2, r);
    if (lane == 0) atomicAdd(&g_gcnt[b], 1.0f);
}

__global__ void divide_kernel(float* __restrict__ out, int G) {
    int i = blockIdx.x * blockDim.x + threadIdx.x;
    if (i < G * OUT_C) {
        float c = g_gcnt[i / OUT_C];
        out[i] = g_gsum[i] / fmaxf(c, 1.0f);
    }
}

// ---------------- launch ----------------
extern "C" void kernel_launch(void* const* d_in, const int* in_sizes, int n_in,
                              void* d_out, int out_size) {
    const float* x   = (const float*)d_in[0];
    const float* W1  = (const float*)d_in[1];
    const float* b1  = (const float*)d_in[2];
    const float* W2  = (const float*)d_in[3];
    const float* b2  = (const float*)d_in[4];
    const int*   ei  = (const int*)d_in[5];   // int32
    const int*   bat = (const int*)d_in[6];

    const int N = in_sizes[0] / IN_C;      // 50000
    const int E = in_sizes[5] / 2;         // 625000
    const int G = out_size / OUT_C;        // 128

    const int* src = ei;
    const int* dst = ei + E;

    void *p_degi, *p_gsum, *p_gcnt, *p_g1, *p_g2, *p_t;
    cudaGetSymbolAddress(&p_degi, g_degi);
    cudaGetSymbolAddress(&p_gsum, g_gsum);
    cudaGetSymbolAddress(&p_gcnt, g_gcnt);
    cudaGetSymbolAddress(&p_g1, g_g1);
    cudaGetSymbolAddress(&p_g2, g_g2);
    cudaGetSymbolAddress(&p_t,  g_t);

    cudaMemsetAsync(p_degi, 0, (size_t)N * sizeof(int));
    cudaMemsetAsync(p_gsum, 0, (size_t)G * OUT_C * sizeof(float));
    cudaMemsetAsync(p_gcnt, 0, (size_t)G * sizeof(float));

    deg_kernel <<<(E + 255) / 256, 256>>>(dst, E);
    scan_kernel<<<1, 1024>>>(N);                       // off + cur + dinv
    fill_kernel<<<(E + 255) / 256, 256>>>(src, dst, E);

    // GEMM1: g1 = dinv * (x @ W1)
    sgemm_kernel<128, 8><<<(N + 127) / 128, 256>>>(x, W1, (float*)p_g1, N);
    // Aggregate 1 (pull) + relu + bias -> t
    gather1_kernel<<<(N + 7) / 8, 256>>>(b1, N);

    // GEMM2: g2 = dinv * (t @ W2)
    sgemm_kernel<64, 4><<<(N + 127) / 128, 256>>>((float*)p_t, W2, (float*)p_g2, N);
    // Aggregate 2 (pull) + bias + pool
    gather2_kernel<<<(N + 7) / 8, 256>>>(bat, b2, N);

    divide_kernel<<<(G * OUT_C + 255) / 256, 256>>>((float*)d_out, G);
}

// round 9
// speedup vs baseline: 1.8484x; 1.8484x over previous
#include <cuda_runtime.h>
#include <cuda_bf16.h>
#include <cstddef>

#define N_NODES   50000
#define N_GRAPHS  128
#define IN_C      128
#define HID_C     128
#define OUT_C     64

// ---------------- device scratch (no allocations allowed) ----------------
__device__ int   g_degi[N_NODES];
__device__ float g_dinv[N_NODES];
__device__ float g_g1  [(size_t)N_NODES * HID_C];   // dinv * (x @ W1)
__device__ float g_acc1[(size_t)N_NODES * HID_C];   // scatter accumulator layer 1
__device__ float g_g2  [(size_t)N_NODES * OUT_C];   // dinv * (t @ W2)
__device__ float g_acc2[(size_t)N_NODES * OUT_C];   // scatter accumulator layer 2
__device__ float g_gsum[N_GRAPHS * OUT_C];
__device__ float g_gcnt[N_GRAPHS];

__device__ __forceinline__ void red_add_v4(float* p, float4 v) {
    asm volatile("red.global.add.v4.f32 [%0], {%1, %2, %3, %4};"
                 :: "l"(p), "f"(v.x), "f"(v.y), "f"(v.z), "f"(v.w)
                 : "memory");
}

// ---------------- degree / dinv ----------------
__global__ void deg_kernel(const int* __restrict__ dst, int E) {
    int e = blockIdx.x * blockDim.x + threadIdx.x;
    if (e < E) atomicAdd(&g_degi[dst[e]], 1);
}

__global__ void dinv_kernel(int N) {
    int i = blockIdx.x * blockDim.x + threadIdx.x;
    if (i < N) g_dinv[i] = rsqrtf((float)(1 + g_degi[i]));  // +1 self-loop
}

// ---------------- double-buffered SGEMM, BM=128 x BN=64 tile ----------------
// C[M, LD] tile at cols [blockIdx.y*64, +64) = dinv ⊙ (A[M,128] @ B[128, LD] slab).
// 256 threads; thread (tx=tid%16, ty=tid/16) computes rows ty*8..+7, cols tx*4..+3.
// FUSE_IN: A row built on the fly = relu(dinv*(acc1+g1)+bias)  (layer-2 input).
template<int LD, bool FUSE_IN>
__global__ void __launch_bounds__(256, 3)
sgemm_kernel(const float* __restrict__ A,
             const float* __restrict__ bias,
             const float* __restrict__ B,
             float* __restrict__ C, int M) {
    __shared__ __align__(16) float As[2][8][128];
    __shared__ __align__(16) float Bs[2][8][64];

    const int tid  = threadIdx.x;
    const int tx   = tid & 15;
    const int ty   = tid >> 4;
    const int row0 = blockIdx.x * 128;
    const int col0 = blockIdx.y * 64;

    const int am = tid >> 1;            // 0..127
    const int ak = (tid & 1) * 4;       // {0,4}
    const int bk  = tid >> 4;           // 0..7 (tid<128 active)
    const int bc4 = tid & 15;           // 0..15
    const bool bAct = (tid < 128);

    float acc[8][4];
#pragma unroll
    for (int i = 0; i < 8; i++)
#pragma unroll
        for (int j = 0; j < 4; j++) acc[i][j] = 0.f;

    auto gloadA = [&](int k0) -> float4 {
        int grow = row0 + am;
        float4 v = make_float4(0.f, 0.f, 0.f, 0.f);
        if (grow < M) {
            if (FUSE_IN) {
                float dv = g_dinv[grow];
                float4 av = *(const float4*)(g_acc1 + (size_t)grow * 128 + k0 + ak);
                float4 gv = *(const float4*)(g_g1   + (size_t)grow * 128 + k0 + ak);
                float4 bv = *(const float4*)(bias + k0 + ak);
                v.x = fmaxf(dv * (av.x + gv.x) + bv.x, 0.f);
                v.y = fmaxf(dv * (av.y + gv.y) + bv.y, 0.f);
                v.z = fmaxf(dv * (av.z + gv.z) + bv.z, 0.f);
                v.w = fmaxf(dv * (av.w + gv.w) + bv.w, 0.f);
            } else {
                v = *(const float4*)(A + (size_t)grow * 128 + k0 + ak);
            }
        }
        return v;
    };
    auto gloadB = [&](int k0) -> float4 {
        if (!bAct) return make_float4(0.f, 0.f, 0.f, 0.f);
        return *(const float4*)(B + (size_t)(k0 + bk) * LD + col0 + bc4 * 4);
    };
    auto storeA = [&](int buf, float4 v) {
        As[buf][ak + 0][am] = v.x;
        As[buf][ak + 1][am] = v.y;
        As[buf][ak + 2][am] = v.z;
        As[buf][ak + 3][am] = v.w;
    };
    auto storeB = [&](int buf, float4 v) {
        if (bAct) *(float4*)(&Bs[buf][bk][bc4 * 4]) = v;
    };

    storeA(0, gloadA(0));
    storeB(0, gloadB(0));
    __syncthreads();

#pragma unroll 1
    for (int t = 0; t < 16; t++) {
        const int cur = t & 1;
        float4 pa, pb;
        if (t < 15) {                      // register-staged prefetch
            pa = gloadA((t + 1) * 8);
            pb = gloadB((t + 1) * 8);
        }
#pragma unroll
        for (int k = 0; k < 8; k++) {
            float a[8];
            float4 a0 = *(const float4*)(&As[cur][k][ty * 8]);
            float4 a1 = *(const float4*)(&As[cur][k][ty * 8 + 4]);
            a[0] = a0.x; a[1] = a0.y; a[2] = a0.z; a[3] = a0.w;
            a[4] = a1.x; a[5] = a1.y; a[6] = a1.z; a[7] = a1.w;
            float4 b0 = *(const float4*)(&Bs[cur][k][tx * 4]);
            float b[4] = {b0.x, b0.y, b0.z, b0.w};
#pragma unroll
            for (int i = 0; i < 8; i++)
#pragma unroll
                for (int j = 0; j < 4; j++) acc[i][j] += a[i] * b[j];
        }
        if (t < 15) {
            storeA(cur ^ 1, pa);
            storeB(cur ^ 1, pb);
        }
        __syncthreads();
    }

    // epilogue: scale by dinv[row]
#pragma unroll
    for (int i = 0; i < 8; i++) {
        int grow = row0 + ty * 8 + i;
        if (grow >= M) break;
        float d = g_dinv[grow];
        float4 v;
        v.x = d * acc[i][0];
        v.y = d * acc[i][1];
        v.z = d * acc[i][2];
        v.w = d * acc[i][3];
        *(float4*)(C + (size_t)grow * LD + col0 + tx * 4) = v;
    }
}

// ---------------- scatter layer 1: acc1[dst] += g1[src] (128 floats/edge) ----------------
__global__ void scatter1_kernel(const int* __restrict__ src,
                                const int* __restrict__ dst,
                                int E) {
    int warp = (blockIdx.x * blockDim.x + threadIdx.x) >> 5;
    int lane = threadIdx.x & 31;
    if (warp >= E) return;
    int s = src[warp];
    int d = dst[warp];
    float4 v = ((const float4*)(g_g1 + (size_t)s * HID_C))[lane];
    red_add_v4(g_acc1 + (size_t)d * HID_C + lane * 4, v);
}

// ---------------- scatter layer 2: acc2[dst] += g2[src] (64 floats/edge) ----------------
__global__ void scatter2_kernel(const int* __restrict__ src,
                                const int* __restrict__ dst,
                                int E) {
    int t = blockIdx.x * blockDim.x + threadIdx.x;
    int e = t >> 4;
    int lane = t & 15;
    if (e >= E) return;
    int s = src[e];
    int d = dst[e];
    float4 v = ((const float4*)(g_g2 + (size_t)s * OUT_C))[lane];
    red_add_v4(g_acc2 + (size_t)d * OUT_C + lane * 4, v);
}

// ---------------- pool: out2 = dinv*(acc2+g2)+b2; RED into graph sums ----------------
__global__ void pool_kernel(const int* __restrict__ batch,
                            const float* __restrict__ b2,
                            int N) {
    int t = blockIdx.x * blockDim.x + threadIdx.x;
    int node = t >> 4;
    int lane = t & 15;
    if (node >= N) return;
    int b = batch[node];
    float dv = g_dinv[node];
    float4 av = ((const float4*)(g_acc2 + (size_t)node * OUT_C))[lane];
    float4 gv = ((const float4*)(g_g2   + (size_t)node * OUT_C))[lane];
    float4 bv = *(const float4*)(b2 + lane * 4);
    float4 r;
    r.x = dv * (av.x + gv.x) + bv.x;
    r.y = dv * (av.y + gv.y) + bv.y;
    r.z = dv * (av.z + gv.z) + bv.z;
    r.w = dv * (av.w + gv.w) + bv.w;
    red_add_v4(g_gsum + b * OUT_C + lane * 4, r);
    if (lane == 0) atomicAdd(&g_gcnt[b], 1.0f);
}

__global__ void divide_kernel(float* __restrict__ out, int G) {
    int i = blockIdx.x * blockDim.x + threadIdx.x;
    if (i < G * OUT_C) {
        float c = g_gcnt[i / OUT_C];
        out[i] = g_gsum[i] / fmaxf(c, 1.0f);
    }
}

// ---------------- launch ----------------
extern "C" void kernel_launch(void* const* d_in, const int* in_sizes, int n_in,
                              void* d_out, int out_size) {
    const float* x   = (const float*)d_in[0];
    const float* W1  = (const float*)d_in[1];
    const float* b1  = (const float*)d_in[2];
    const float* W2  = (const float*)d_in[3];
    const float* b2  = (const float*)d_in[4];
    const int*   ei  = (const int*)d_in[5];   // int32
    const int*   bat = (const int*)d_in[6];

    const int N = in_sizes[0] / IN_C;      // 50000
    const int E = in_sizes[5] / 2;         // 625000
    const int G = out_size / OUT_C;        // 128

    const int* src = ei;
    const int* dst = ei + E;

    void *p_degi, *p_acc1, *p_acc2, *p_gsum, *p_gcnt, *p_g1, *p_g2;
    cudaGetSymbolAddress(&p_degi, g_degi);
    cudaGetSymbolAddress(&p_acc1, g_acc1);
    cudaGetSymbolAddress(&p_acc2, g_acc2);
    cudaGetSymbolAddress(&p_gsum, g_gsum);
    cudaGetSymbolAddress(&p_gcnt, g_gcnt);
    cudaGetSymbolAddress(&p_g1, g_g1);
    cudaGetSymbolAddress(&p_g2, g_g2);

    cudaMemsetAsync(p_degi, 0, (size_t)N * sizeof(int));
    cudaMemsetAsync(p_acc1, 0, (size_t)N * HID_C * sizeof(float));
    cudaMemsetAsync(p_acc2, 0, (size_t)N * OUT_C * sizeof(float));
    cudaMemsetAsync(p_gsum, 0, (size_t)G * OUT_C * sizeof(float));
    cudaMemsetAsync(p_gcnt, 0, (size_t)G * sizeof(float));

    deg_kernel <<<(E + 255) / 256, 256>>>(dst, E);
    dinv_kernel<<<(N + 255) / 256, 256>>>(N);

    // GEMM1: g1 = dinv * (x @ W1)   (N split across gridDim.y = 2)
    {
        dim3 grid((N + 127) / 128, 2);
        sgemm_kernel<128, false><<<grid, 256>>>(x, nullptr, W1, (float*)p_g1, N);
    }
    scatter1_kernel<<<(E + 7) / 8, 256>>>(src, dst, E);

    // GEMM2: g2 = dinv * (relu(dinv*(acc1+g1)+b1) @ W2)  (input fused)
    {
        dim3 grid((N + 127) / 128, 1);
        sgemm_kernel<64, true><<<grid, 256>>>(nullptr, b1, W2, (float*)p_g2, N);
    }
    scatter2_kernel<<<(E + 15) / 16, 256>>>(src, dst, E);

    pool_kernel<<<(N + 15) / 16, 256>>>(bat, b2, N);
    divide_kernel<<<(G * OUT_C + 255) / 256, 256>>>((float*)d_out, G);
}

// round 10
// speedup vs baseline: 2.3836x; 1.2895x over previous
#include <cuda_runtime.h>
#include <cuda_fp16.h>
#include <cstddef>
#include <cstdint>

#define N_NODES   50000
#define N_GRAPHS  128
#define IN_C      128
#define HID_C     128
#define OUT_C     64

// ---------------- device scratch (no allocations allowed) ----------------
__device__ int    g_degi[N_NODES];
__device__ float  g_dinv[N_NODES];
__device__ float  g_g1  [(size_t)N_NODES * HID_C];   // fp32 messages L1 (for gemm2 input)
__device__ __half g_g1h [(size_t)N_NODES * HID_C];   // fp16 messages L1 (for scatter)
__device__ __half g_acc1[(size_t)N_NODES * HID_C];   // fp16 scatter accumulator L1
__device__ __half g_g2h [(size_t)N_NODES * OUT_C];   // fp16 messages L2
__device__ __half g_acc2[(size_t)N_NODES * OUT_C];   // fp16 scatter accumulator L2
__device__ float  g_gsum[N_GRAPHS * OUT_C];
__device__ float  g_gcnt[N_GRAPHS];

__device__ __forceinline__ void red_add_v4(float* p, float4 v) {
    asm volatile("red.global.add.v4.f32 [%0], {%1, %2, %3, %4};"
                 :: "l"(p), "f"(v.x), "f"(v.y), "f"(v.z), "f"(v.w)
                 : "memory");
}
// 8 halfs per op (16B) — sm_90+
__device__ __forceinline__ void red_add_v4h(__half* p, uint4 v) {
    asm volatile("red.global.add.noftz.v4.f16x2 [%0], {%1, %2, %3, %4};"
                 :: "l"(p), "r"(v.x), "r"(v.y), "r"(v.z), "r"(v.w)
                 : "memory");
}

// ---------------- degree / dinv ----------------
__global__ void deg_kernel(const int* __restrict__ dst, int E) {
    int e = blockIdx.x * blockDim.x + threadIdx.x;
    if (e < E) atomicAdd(&g_degi[dst[e]], 1);
}

__global__ void dinv_kernel(int N) {
    int i = blockIdx.x * blockDim.x + threadIdx.x;
    if (i < N) g_dinv[i] = rsqrtf((float)(1 + g_degi[i]));  // +1 self-loop
}

// ---------------- double-buffered SGEMM, BM=128 x BN=64 tile ----------------
// C tile at cols [blockIdx.y*64, +64) = dinv ⊙ (A[M,128] @ B[128, LD] slab).
// WRITE32: also write fp32 copy (layer-1 path). C16 always written (fp16 messages).
// FUSE_IN: A row built on the fly = relu(dinv*(acc1h+g1)+bias)  (layer-2 input).
template<int LD, bool FUSE_IN, bool WRITE32>
__global__ void __launch_bounds__(256, 3)
sgemm_kernel(const float* __restrict__ A,
             const float* __restrict__ bias,
             const float* __restrict__ B,
             float* __restrict__ C32,
             __half* __restrict__ C16, int M) {
    __shared__ __align__(16) float As[2][8][128];
    __shared__ __align__(16) float Bs[2][8][64];

    const int tid  = threadIdx.x;
    const int tx   = tid & 15;
    const int ty   = tid >> 4;
    const int row0 = blockIdx.x * 128;
    const int col0 = blockIdx.y * 64;

    const int am = tid >> 1;            // 0..127
    const int ak = (tid & 1) * 4;       // {0,4}
    const int bk  = tid >> 4;           // 0..7 (tid<128 active)
    const int bc4 = tid & 15;           // 0..15
    const bool bAct = (tid < 128);

    float acc[8][4];
#pragma unroll
    for (int i = 0; i < 8; i++)
#pragma unroll
        for (int j = 0; j < 4; j++) acc[i][j] = 0.f;

    auto gloadA = [&](int k0) -> float4 {
        int grow = row0 + am;
        float4 v = make_float4(0.f, 0.f, 0.f, 0.f);
        if (grow < M) {
            if (FUSE_IN) {
                float dv = g_dinv[grow];
                uint2 au = *(const uint2*)(g_acc1 + (size_t)grow * 128 + k0 + ak);
                __half2 ah0 = *reinterpret_cast<__half2*>(&au.x);
                __half2 ah1 = *reinterpret_cast<__half2*>(&au.y);
                float2 a0 = __half22float2(ah0);
                float2 a1 = __half22float2(ah1);
                float4 gv = *(const float4*)(g_g1 + (size_t)grow * 128 + k0 + ak);
                float4 bv = *(const float4*)(bias + k0 + ak);
                v.x = fmaxf(dv * (a0.x + gv.x) + bv.x, 0.f);
                v.y = fmaxf(dv * (a0.y + gv.y) + bv.y, 0.f);
                v.z = fmaxf(dv * (a1.x + gv.z) + bv.z, 0.f);
                v.w = fmaxf(dv * (a1.y + gv.w) + bv.w, 0.f);
            } else {
                v = *(const float4*)(A + (size_t)grow * 128 + k0 + ak);
            }
        }
        return v;
    };
    auto gloadB = [&](int k0) -> float4 {
        if (!bAct) return make_float4(0.f, 0.f, 0.f, 0.f);
        return *(const float4*)(B + (size_t)(k0 + bk) * LD + col0 + bc4 * 4);
    };
    auto storeA = [&](int buf, float4 v) {
        As[buf][ak + 0][am] = v.x;
        As[buf][ak + 1][am] = v.y;
        As[buf][ak + 2][am] = v.z;
        As[buf][ak + 3][am] = v.w;
    };
    auto storeB = [&](int buf, float4 v) {
        if (bAct) *(float4*)(&Bs[buf][bk][bc4 * 4]) = v;
    };

    storeA(0, gloadA(0));
    storeB(0, gloadB(0));
    __syncthreads();

#pragma unroll 1
    for (int t = 0; t < 16; t++) {
        const int cur = t & 1;
        float4 pa, pb;
        if (t < 15) {
            pa = gloadA((t + 1) * 8);
            pb = gloadB((t + 1) * 8);
        }
#pragma unroll
        for (int k = 0; k < 8; k++) {
            float a[8];
            float4 a0 = *(const float4*)(&As[cur][k][ty * 8]);
            float4 a1 = *(const float4*)(&As[cur][k][ty * 8 + 4]);
            a[0] = a0.x; a[1] = a0.y; a[2] = a0.z; a[3] = a0.w;
            a[4] = a1.x; a[5] = a1.y; a[6] = a1.z; a[7] = a1.w;
            float4 b0 = *(const float4*)(&Bs[cur][k][tx * 4]);
            float b[4] = {b0.x, b0.y, b0.z, b0.w};
#pragma unroll
            for (int i = 0; i < 8; i++)
#pragma unroll
                for (int j = 0; j < 4; j++) acc[i][j] += a[i] * b[j];
        }
        if (t < 15) {
            storeA(cur ^ 1, pa);
            storeB(cur ^ 1, pb);
        }
        __syncthreads();
    }

#pragma unroll
    for (int i = 0; i < 8; i++) {
        int grow = row0 + ty * 8 + i;
        if (grow >= M) break;
        float d = g_dinv[grow];
        float4 v;
        v.x = d * acc[i][0];
        v.y = d * acc[i][1];
        v.z = d * acc[i][2];
        v.w = d * acc[i][3];
        if (WRITE32)
            *(float4*)(C32 + (size_t)grow * LD + col0 + tx * 4) = v;
        __half2 h0 = __floats2half2_rn(v.x, v.y);
        __half2 h1 = __floats2half2_rn(v.z, v.w);
        uint2 u;
        u.x = *reinterpret_cast<unsigned*>(&h0);
        u.y = *reinterpret_cast<unsigned*>(&h1);
        *(uint2*)(C16 + (size_t)grow * LD + col0 + tx * 4) = u;
    }
}

// ---------------- scatter layer 1: acc1[dst] += g1h[src] (128 halfs/edge, 16 lanes) ----------------
__global__ void scatter1_kernel(const int* __restrict__ src,
                                const int* __restrict__ dst,
                                int E) {
    int t = blockIdx.x * blockDim.x + threadIdx.x;
    int e = t >> 4;
    int lane = t & 15;
    if (e >= E) return;
    int s = src[e];
    int d = dst[e];
    uint4 v = ((const uint4*)(g_g1h + (size_t)s * HID_C))[lane];  // 8 halfs
    red_add_v4h(g_acc1 + (size_t)d * HID_C + lane * 8, v);
}

// ---------------- scatter layer 2: acc2[dst] += g2h[src] (64 halfs/edge, 8 lanes) ----------------
__global__ void scatter2_kernel(const int* __restrict__ src,
                                const int* __restrict__ dst,
                                int E) {
    int t = blockIdx.x * blockDim.x + threadIdx.x;
    int e = t >> 3;
    int lane = t & 7;
    if (e >= E) return;
    int s = src[e];
    int d = dst[e];
    uint4 v = ((const uint4*)(g_g2h + (size_t)s * OUT_C))[lane];  // 8 halfs
    red_add_v4h(g_acc2 + (size_t)d * OUT_C + lane * 8, v);
}

// ---------------- pool: out2 = dinv*(acc2+g2h)+b2; RED into graph sums ----------------
__global__ void pool_kernel(const int* __restrict__ batch,
                            const float* __restrict__ b2,
                            int N) {
    int t = blockIdx.x * blockDim.x + threadIdx.x;
    int node = t >> 4;
    int lane = t & 15;
    if (node >= N) return;
    int b = batch[node];
    float dv = g_dinv[node];
    uint2 au = ((const uint2*)(g_acc2 + (size_t)node * OUT_C))[lane];
    uint2 gu = ((const uint2*)(g_g2h  + (size_t)node * OUT_C))[lane];
    __half2 ah0 = *reinterpret_cast<__half2*>(&au.x);
    __half2 ah1 = *reinterpret_cast<__half2*>(&au.y);
    __half2 gh0 = *reinterpret_cast<__half2*>(&gu.x);
    __half2 gh1 = *reinterpret_cast<__half2*>(&gu.y);
    float2 a0 = __half22float2(ah0), a1 = __half22float2(ah1);
    float2 g0 = __half22float2(gh0), g1 = __half22float2(gh1);
    float4 bv = *(const float4*)(b2 + lane * 4);
    float4 r;
    r.x = dv * (a0.x + g0.x) + bv.x;
    r.y = dv * (a0.y + g0.y) + bv.y;
    r.z = dv * (a1.x + g1.x) + bv.z;
    r.w = dv * (a1.y + g1.y) + bv.w;
    red_add_v4(g_gsum + b * OUT_C + lane * 4, r);
    if (lane == 0) atomicAdd(&g_gcnt[b], 1.0f);
}

__global__ void divide_kernel(float* __restrict__ out, int G) {
    int i = blockIdx.x * blockDim.x + threadIdx.x;
    if (i < G * OUT_C) {
        float c = g_gcnt[i / OUT_C];
        out[i] = g_gsum[i] / fmaxf(c, 1.0f);
    }
}

// ---------------- launch ----------------
extern "C" void kernel_launch(void* const* d_in, const int* in_sizes, int n_in,
                              void* d_out, int out_size) {
    const float* x   = (const float*)d_in[0];
    const float* W1  = (const float*)d_in[1];
    const float* b1  = (const float*)d_in[2];
    const float* W2  = (const float*)d_in[3];
    const float* b2  = (const float*)d_in[4];
    const int*   ei  = (const int*)d_in[5];   // int32
    const int*   bat = (const int*)d_in[6];

    const int N = in_sizes[0] / IN_C;      // 50000
    const int E = in_sizes[5] / 2;         // 625000
    const int G = out_size / OUT_C;        // 128

    const int* src = ei;
    const int* dst = ei + E;

    void *p_degi, *p_acc1, *p_acc2, *p_gsum, *p_gcnt, *p_g1, *p_g1h, *p_g2h;
    cudaGetSymbolAddress(&p_degi, g_degi);
    cudaGetSymbolAddress(&p_acc1, g_acc1);
    cudaGetSymbolAddress(&p_acc2, g_acc2);
    cudaGetSymbolAddress(&p_gsum, g_gsum);
    cudaGetSymbolAddress(&p_gcnt, g_gcnt);
    cudaGetSymbolAddress(&p_g1,  g_g1);
    cudaGetSymbolAddress(&p_g1h, g_g1h);
    cudaGetSymbolAddress(&p_g2h, g_g2h);

    cudaMemsetAsync(p_degi, 0, (size_t)N * sizeof(int));
    cudaMemsetAsync(p_acc1, 0, (size_t)N * HID_C * sizeof(__half));
    cudaMemsetAsync(p_acc2, 0, (size_t)N * OUT_C * sizeof(__half));
    cudaMemsetAsync(p_gsum, 0, (size_t)G * OUT_C * sizeof(float));
    cudaMemsetAsync(p_gcnt, 0, (size_t)G * sizeof(float));

    deg_kernel <<<(E + 255) / 256, 256>>>(dst, E);
    dinv_kernel<<<(N + 255) / 256, 256>>>(N);

    // GEMM1: g1/g1h = dinv * (x @ W1)   (N split across gridDim.y = 2)
    {
        dim3 grid((N + 127) / 128, 2);
        sgemm_kernel<128, false, true><<<grid, 256>>>(
            x, nullptr, W1, (float*)p_g1, (__half*)p_g1h, N);
    }
    scatter1_kernel<<<((size_t)E * 16 + 255) / 256, 256>>>(src, dst, E);

    // GEMM2: g2h = dinv * (relu(dinv*(acc1+g1)+b1) @ W2)  (input fused, fp16-only out)
    {
        dim3 grid((N + 127) / 128, 1);
        sgemm_kernel<64, true, false><<<grid, 256>>>(
            nullptr, b1, W2, nullptr, (__half*)p_g2h, N);
    }
    scatter2_kernel<<<((size_t)E * 8 + 255) / 256, 256>>>(src, dst, E);

    pool_kernel<<<(N + 15) / 16, 256>>>(bat, b2, N);
    divide_kernel<<<(G * OUT_C + 255) / 256, 256>>>((float*)d_out, G);
}

// round 12
// speedup vs baseline: 3.5675x; 1.4967x over previous
#include <cuda_runtime.h>
#include <cuda_fp16.h>
#include <mma.h>
#include <cstddef>
#include <cstdint>

using namespace nvcuda;

#define N_NODES   50000
#define N_GRAPHS  128
#define IN_C      128
#define HID_C     128
#define OUT_C     64

// ---------------- device scratch (no allocations allowed) ----------------
__device__ int    g_degi[N_NODES];
__device__ float  g_dinv[N_NODES];
__device__ __half g_g1h [(size_t)N_NODES * HID_C];   // fp16 messages L1
__device__ __half g_acc1[(size_t)N_NODES * HID_C];   // fp16 scatter accumulator L1
__device__ __half g_g2h [(size_t)N_NODES * OUT_C];   // fp16 messages L2
__device__ __half g_acc2[(size_t)N_NODES * OUT_C];   // fp16 scatter accumulator L2
__device__ float  g_gsum[N_GRAPHS * OUT_C];
__device__ float  g_gcnt[N_GRAPHS];

__device__ __forceinline__ void red_add_v4(float* p, float4 v) {
    asm volatile("red.global.add.v4.f32 [%0], {%1, %2, %3, %4};"
                 :: "l"(p), "f"(v.x), "f"(v.y), "f"(v.z), "f"(v.w)
                 : "memory");
}
// 8 halfs per op (16B) — sm_90+
__device__ __forceinline__ void red_add_v4h(__half* p, uint4 v) {
    asm volatile("red.global.add.noftz.v4.f16x2 [%0], {%1, %2, %3, %4};"
                 :: "l"(p), "r"(v.x), "r"(v.y), "r"(v.z), "r"(v.w)
                 : "memory");
}
__device__ __forceinline__ uint4 f8_to_h8(float4 a, float4 b) {
    __half2 h0 = __floats2half2_rn(a.x, a.y);
    __half2 h1 = __floats2half2_rn(a.z, a.w);
    __half2 h2 = __floats2half2_rn(b.x, b.y);
    __half2 h3 = __floats2half2_rn(b.z, b.w);
    uint4 u;
    u.x = *reinterpret_cast<unsigned*>(&h0);
    u.y = *reinterpret_cast<unsigned*>(&h1);
    u.z = *reinterpret_cast<unsigned*>(&h2);
    u.w = *reinterpret_cast<unsigned*>(&h3);
    return u;
}

// ---------------- degree / dinv ----------------
__global__ void deg_kernel(const int* __restrict__ dst, int E) {
    int e = blockIdx.x * blockDim.x + threadIdx.x;
    if (e < E) atomicAdd(&g_degi[dst[e]], 1);
}

__global__ void dinv_kernel(int N) {
    int i = blockIdx.x * blockDim.x + threadIdx.x;
    if (i < N) g_dinv[i] = rsqrtf((float)(1 + g_degi[i]));  // +1 self-loop
}

// ---------------- fp16 HMMA GEMM: C16 = dinv ⊙ (A[M,128] @ B[128,LD]) ----------------
// BM=128, 256 threads = 8 warps as 4(m) x 2(n); warp covers 32 rows x LD/2 cols.
// K=128 staged entirely in smem (8 k16 steps). A,B converted fp32->fp16 on load.
// FUSE_IN: A row = relu(dinv*(acc1+g1h)+bias)  (layer-2 input, fp16 sources).
template<int LD, bool FUSE_IN>
__global__ void __launch_bounds__(256)
hgemm_kernel(const float* __restrict__ A,
             const float* __restrict__ bias,
             const float* __restrict__ B,
             __half* __restrict__ C16, int M) {
    extern __shared__ __half sm[];
    constexpr int LDA = 136;          // 128 + 8 pad
    constexpr int LDB = LD + 8;
    constexpr int NT  = LD / 32;      // n-tiles of 16 per warp
    __half* As = sm;                  // [128][136]
    __half* Bs = sm + 128 * LDA;      // [128][LDB]

    const int tid    = threadIdx.x;
    const int wid    = tid >> 5;
    const int lane   = tid & 31;
    const int warp_m = wid >> 1;      // 0..3 -> rows warp_m*32
    const int warp_n = wid & 1;       // 0..1 -> cols warp_n*(LD/2)
    const int row0   = blockIdx.x * 128;

    // ---- stage A (convert to fp16) ----
#pragma unroll
    for (int it = 0; it < 8; it++) {
        int chunk = tid + it * 256;
        int r  = chunk >> 4;          // /16 chunks per row
        int c8 = chunk & 15;
        int grow = row0 + r;
        uint4 u;
        if (grow < M) {
            if (FUSE_IN) {
                float dv = g_dinv[grow];
                uint4 au = ((const uint4*)(g_acc1 + (size_t)grow * 128))[c8];
                uint4 gu = ((const uint4*)(g_g1h  + (size_t)grow * 128))[c8];
                float4 bv0 = *(const float4*)(bias + c8 * 8);
                float4 bv1 = *(const float4*)(bias + c8 * 8 + 4);
                const __half2* ah = (const __half2*)&au;
                const __half2* gh = (const __half2*)&gu;
                float4 lo, hi;
                float2 t0 = __half22float2(ah[0]), s0 = __half22float2(gh[0]);
                float2 t1 = __half22float2(ah[1]), s1 = __half22float2(gh[1]);
                float2 t2 = __half22float2(ah[2]), s2 = __half22float2(gh[2]);
                float2 t3 = __half22float2(ah[3]), s3 = __half22float2(gh[3]);
                lo.x = fmaxf(dv * (t0.x + s0.x) + bv0.x, 0.f);
                lo.y = fmaxf(dv * (t0.y + s0.y) + bv0.y, 0.f);
                lo.z = fmaxf(dv * (t1.x + s1.x) + bv0.z, 0.f);
                lo.w = fmaxf(dv * (t1.y + s1.y) + bv0.w, 0.f);
                hi.x = fmaxf(dv * (t2.x + s2.x) + bv1.x, 0.f);
                hi.y = fmaxf(dv * (t2.y + s2.y) + bv1.y, 0.f);
                hi.z = fmaxf(dv * (t3.x + s3.x) + bv1.z, 0.f);
                hi.w = fmaxf(dv * (t3.y + s3.y) + bv1.w, 0.f);
                u = f8_to_h8(lo, hi);
            } else {
                float4 lo = *(const float4*)(A + (size_t)grow * 128 + c8 * 8);
                float4 hi = *(const float4*)(A + (size_t)grow * 128 + c8 * 8 + 4);
                u = f8_to_h8(lo, hi);
            }
        } else {
            u = make_uint4(0, 0, 0, 0);
        }
        *(uint4*)(As + r * LDA + c8 * 8) = u;
    }
    // ---- stage B (convert to fp16): 128*LD halfs ----
    constexpr int BCH = 128 * LD / 8 / 256;   // 8 (LD=128) or 4 (LD=64)
#pragma unroll
    for (int it = 0; it < BCH; it++) {
        int chunk = tid + it * 256;
        int r  = chunk / (LD / 8);
        int c8 = chunk % (LD / 8);
        float4 lo = *(const float4*)(B + (size_t)r * LD + c8 * 8);
        float4 hi = *(const float4*)(B + (size_t)r * LD + c8 * 8 + 4);
        *(uint4*)(Bs + r * LDB + c8 * 8) = f8_to_h8(lo, hi);
    }
    __syncthreads();

    // ---- MMA: 8 k-steps ----
    wmma::fragment<wmma::accumulator, 16, 16, 16, float> acc[2][NT];
#pragma unroll
    for (int i = 0; i < 2; i++)
#pragma unroll
        for (int nt = 0; nt < NT; nt++) wmma::fill_fragment(acc[i][nt], 0.f);

#pragma unroll
    for (int k = 0; k < 8; k++) {
        wmma::fragment<wmma::matrix_a, 16, 16, 16, __half, wmma::row_major> a0, a1;
        wmma::load_matrix_sync(a0, As + (warp_m * 32 +  0) * LDA + k * 16, LDA);
        wmma::load_matrix_sync(a1, As + (warp_m * 32 + 16) * LDA + k * 16, LDA);
#pragma unroll
        for (int nt = 0; nt < NT; nt++) {
            wmma::fragment<wmma::matrix_b, 16, 16, 16, __half, wmma::row_major> b;
            wmma::load_matrix_sync(b, Bs + (k * 16) * LDB + warp_n * (LD / 2) + nt * 16, LDB);
            wmma::mma_sync(acc[0][nt], a0, b, acc[0][nt]);
            wmma::mma_sync(acc[1][nt], a1, b, acc[1][nt]);
        }
    }
    __syncthreads();

    // ---- epilogue: per-warp staging (ldm=16, 16B-multiple — WMMA contract), dinv, fp16 store ----
    float* wbuf = (float*)(sm) + wid * 256;    // 16x16 floats per warp, 1 KB aligned
#pragma unroll
    for (int i = 0; i < 2; i++) {
#pragma unroll
        for (int nt = 0; nt < NT; nt++) {
            wmma::store_matrix_sync(wbuf, acc[i][nt], 16, wmma::mem_row_major);
            __syncwarp();
            int r  = lane >> 1;
            int c8 = (lane & 1) * 8;
            int grow = row0 + warp_m * 32 + i * 16 + r;
            if (grow < M) {
                float d = g_dinv[grow];
                const float* p = wbuf + r * 16 + c8;
                float4 lo = make_float4(d * p[0], d * p[1], d * p[2], d * p[3]);
                float4 hi = make_float4(d * p[4], d * p[5], d * p[6], d * p[7]);
                int col = warp_n * (LD / 2) + nt * 16 + c8;
                *(uint4*)(C16 + (size_t)grow * LD + col) = f8_to_h8(lo, hi);
            }
            __syncwarp();
        }
    }
}

// ---------------- scatter layer 1: acc1[dst] += g1h[src] (128 halfs/edge, 16 lanes) ----------------
__global__ void scatter1_kernel(const int* __restrict__ src,
                                const int* __restrict__ dst,
                                int E) {
    int t = blockIdx.x * blockDim.x + threadIdx.x;
    int e = t >> 4;
    int lane = t & 15;
    if (e >= E) return;
    int s = src[e];
    int d = dst[e];
    uint4 v = ((const uint4*)(g_g1h + (size_t)s * HID_C))[lane];  // 8 halfs
    red_add_v4h(g_acc1 + (size_t)d * HID_C + lane * 8, v);
}

// ---------------- scatter layer 2: acc2[dst] += g2h[src] (64 halfs/edge, 8 lanes) ----------------
__global__ void scatter2_kernel(const int* __restrict__ src,
                                const int* __restrict__ dst,
                                int E) {
    int t = blockIdx.x * blockDim.x + threadIdx.x;
    int e = t >> 3;
    int lane = t & 7;
    if (e >= E) return;
    int s = src[e];
    int d = dst[e];
    uint4 v = ((const uint4*)(g_g2h + (size_t)s * OUT_C))[lane];  // 8 halfs
    red_add_v4h(g_acc2 + (size_t)d * OUT_C + lane * 8, v);
}

// ---------------- pool: out2 = dinv*(acc2+g2h)+b2; RED into graph sums ----------------
__global__ void pool_kernel(const int* __restrict__ batch,
                            const float* __restrict__ b2,
                            int N) {
    int t = blockIdx.x * blockDim.x + threadIdx.x;
    int node = t >> 4;
    int lane = t & 15;
    if (node >= N) return;
    int b = batch[node];
    float dv = g_dinv[node];
    uint2 au = ((const uint2*)(g_acc2 + (size_t)node * OUT_C))[lane];
    uint2 gu = ((const uint2*)(g_g2h  + (size_t)node * OUT_C))[lane];
    __half2 ah0 = *reinterpret_cast<__half2*>(&au.x);
    __half2 ah1 = *reinterpret_cast<__half2*>(&au.y);
    __half2 gh0 = *reinterpret_cast<__half2*>(&gu.x);
    __half2 gh1 = *reinterpret_cast<__half2*>(&gu.y);
    float2 a0 = __half22float2(ah0), a1 = __half22float2(ah1);
    float2 g0 = __half22float2(gh0), g1 = __half22float2(gh1);
    float4 bv = *(const float4*)(b2 + lane * 4);
    float4 r;
    r.x = dv * (a0.x + g0.x) + bv.x;
    r.y = dv * (a0.y + g0.y) + bv.y;
    r.z = dv * (a1.x + g1.x) + bv.z;
    r.w = dv * (a1.y + g1.y) + bv.w;
    red_add_v4(g_gsum + b * OUT_C + lane * 4, r);
    if (lane == 0) atomicAdd(&g_gcnt[b], 1.0f);
}

__global__ void divide_kernel(float* __restrict__ out, int G) {
    int i = blockIdx.x * blockDim.x + threadIdx.x;
    if (i < G * OUT_C) {
        float c = g_gcnt[i / OUT_C];
        out[i] = g_gsum[i] / fmaxf(c, 1.0f);
    }
}

// ---------------- launch ----------------
extern "C" void kernel_launch(void* const* d_in, const int* in_sizes, int n_in,
                              void* d_out, int out_size) {
    const float* x   = (const float*)d_in[0];
    const float* W1  = (const float*)d_in[1];
    const float* b1  = (const float*)d_in[2];
    const float* W2  = (const float*)d_in[3];
    const float* b2  = (const float*)d_in[4];
    const int*   ei  = (const int*)d_in[5];   // int32
    const int*   bat = (const int*)d_in[6];

    const int N = in_sizes[0] / IN_C;      // 50000
    const int E = in_sizes[5] / 2;         // 625000
    const int G = out_size / OUT_C;        // 128

    const int* src = ei;
    const int* dst = ei + E;

    void *p_degi, *p_acc1, *p_acc2, *p_gsum, *p_gcnt, *p_g1h, *p_g2h;
    cudaGetSymbolAddress(&p_degi, g_degi);
    cudaGetSymbolAddress(&p_acc1, g_acc1);
    cudaGetSymbolAddress(&p_acc2, g_acc2);
    cudaGetSymbolAddress(&p_gsum, g_gsum);
    cudaGetSymbolAddress(&p_gcnt, g_gcnt);
    cudaGetSymbolAddress(&p_g1h, g_g1h);
    cudaGetSymbolAddress(&p_g2h, g_g2h);

    cudaMemsetAsync(p_degi, 0, (size_t)N * sizeof(int));
    cudaMemsetAsync(p_acc1, 0, (size_t)N * HID_C * sizeof(__half));
    cudaMemsetAsync(p_acc2, 0, (size_t)N * OUT_C * sizeof(__half));
    cudaMemsetAsync(p_gsum, 0, (size_t)G * OUT_C * sizeof(float));
    cudaMemsetAsync(p_gcnt, 0, (size_t)G * sizeof(float));

    deg_kernel <<<(E + 255) / 256, 256>>>(dst, E);
    dinv_kernel<<<(N + 255) / 256, 256>>>(N);

    // GEMM1: g1h = dinv * (x @ W1)
    {
        const int smem = (128 * 136 + 128 * (128 + 8)) * (int)sizeof(__half);
        cudaFuncSetAttribute(hgemm_kernel<128, false>,
                             cudaFuncAttributeMaxDynamicSharedMemorySize, smem);
        hgemm_kernel<128, false><<<(N + 127) / 128, 256, smem>>>(
            x, nullptr, W1, (__half*)p_g1h, N);
    }
    scatter1_kernel<<<((size_t)E * 16 + 255) / 256, 256>>>(src, dst, E);

    // GEMM2: g2h = dinv * (relu(dinv*(acc1+g1h)+b1) @ W2)
    {
        const int smem = (128 * 136 + 128 * (64 + 8)) * (int)sizeof(__half);
        cudaFuncSetAttribute(hgemm_kernel<64, true>,
                             cudaFuncAttributeMaxDynamicSharedMemorySize, smem);
        hgemm_kernel<64, true><<<(N + 127) / 128, 256, smem>>>(
            nullptr, b1, W2, (__half*)p_g2h, N);
    }
    scatter2_kernel<<<((size_t)E * 8 + 255) / 256, 256>>>(src, dst, E);

    pool_kernel<<<(N + 15) / 16, 256>>>(bat, b2, N);
    divide_kernel<<<(G * OUT_C + 255) / 256, 256>>>((float*)d_out, G);
}